// round 17
// baseline (speedup 1.0000x reference)
#include <cuda_runtime.h>
#include <cuda_fp16.h>
#include <cstdint>
#include <cstddef>

#define BATCH 64
#define DIM 512
#define MAT (DIM * DIM)
#define NUM_ITER 5
#define BK 32
#define NSTAGE (DIM / BK)   // 16
// row-group layout (u32): AH(16) | AFh(8) | AFl(8) | BH(16) | BFh(8) | BFl(8) | pad(4)
#define GSTR 68
#define O_AH 0
#define O_AFH 16
#define O_AFL 24
#define O_BH 32
#define O_BFH 48
#define O_BFL 56
#define TSTR 132            // transpose buffer row stride in u32
#define NBUF 3
#define LSCALE 4096.0f
#define INVLS  0.000244140625f

typedef unsigned short u16;

// ---------------- device scratch: per matrix: fp16 H plane + fp8 h/l planes ----------------
__device__ u16  g_YH[2][(size_t)BATCH * MAT];
__device__ char g_YFh[2][(size_t)BATCH * MAT];
__device__ char g_YFl[2][(size_t)BATCH * MAT];
__device__ u16  g_ZH[2][(size_t)BATCH * MAT];
__device__ char g_ZFh[2][(size_t)BATCH * MAT];
__device__ char g_ZFl[2][(size_t)BATCH * MAT];
__device__ u16  g_TH[(size_t)BATCH * MAT];
__device__ char g_TFh[(size_t)BATCH * MAT];
__device__ char g_TFl[(size_t)BATCH * MAT];
__device__ float g_norm[BATCH];

// upper-triangular tile pairs for 4x4 grid of 128-wide tiles
__constant__ int c_ti[10] = {0, 0, 0, 0, 1, 1, 1, 2, 2, 3};
__constant__ int c_tj[10] = {0, 1, 2, 3, 1, 2, 3, 2, 3, 3};

#define STAGE_U32 (128 * GSTR)                 // 8704
#define SMEM_BYTES (NBUF * STAGE_U32 * 4)      // 104448 (2 CTAs/SM; >= 128*TSTR*4)

// ---------------- helpers ----------------
__device__ __forceinline__ uint32_t smem_u32(const void* p) {
    uint32_t a;
    asm("{ .reg .u64 t; cvta.to.shared.u64 t, %1; cvt.u32.u64 %0, t; }" : "=r"(a) : "l"(p));
    return a;
}
__device__ __forceinline__ void cp16(uint32_t dst, const void* src) {
    asm volatile("cp.async.cg.shared.global [%0], [%1], 16;" :: "r"(dst), "l"(src));
}
// pack 2 floats -> f16x2 (low half = v0)
__device__ __forceinline__ uint32_t f16pack(float v0, float v1) {
    __half2 h = __floats2half2_rn(v0, v1);
    return *reinterpret_cast<uint32_t*>(&h);
}
__device__ __forceinline__ float2 f16dec(uint32_t p) {
    __half2 h = *reinterpret_cast<__half2*>(&p);
    return __half22float2(h);    // .x = low half
}
// pack 2 floats -> 2 e4m3 (low byte = e_even)
__device__ __forceinline__ uint32_t pk_e4m3(float e_even, float e_odd) {
    unsigned short r;
    asm("cvt.rn.satfinite.e4m3x2.f32 %0, %1, %2;" : "=h"(r) : "f"(e_odd), "f"(e_even));
    return (uint32_t)r;
}
__device__ __forceinline__ float2 e4m3_dec2(uint32_t pk) {
    unsigned short p = (unsigned short)pk;
    uint32_t h2;
    asm("cvt.rn.f16x2.e4m3x2 %0, %1;" : "=r"(h2) : "h"(p));
    __half2 hv = *reinterpret_cast<__half2*>(&h2);
    return __half22float2(hv);   // .x = low byte (even elem)
}
__device__ __forceinline__ void mma_f16(float* c, uint32_t a0, uint32_t a1, uint32_t a2,
                                        uint32_t a3, uint32_t b0, uint32_t b1) {
    asm volatile(
        "mma.sync.aligned.m16n8k16.row.col.f32.f16.f16.f32 "
        "{%0,%1,%2,%3}, {%4,%5,%6,%7}, {%8,%9}, {%0,%1,%2,%3};"
        : "+f"(c[0]), "+f"(c[1]), "+f"(c[2]), "+f"(c[3])
        : "r"(a0), "r"(a1), "r"(a2), "r"(a3), "r"(b0), "r"(b1));
}
__device__ __forceinline__ void mma_e4m3(float* c, uint32_t a0, uint32_t a1, uint32_t a2,
                                         uint32_t a3, uint32_t b0, uint32_t b1) {
    asm volatile(
        "mma.sync.aligned.m16n8k32.row.col.f32.e4m3.e4m3.f32 "
        "{%0,%1,%2,%3}, {%4,%5,%6,%7}, {%8,%9}, {%0,%1,%2,%3};"
        : "+f"(c[0]), "+f"(c[1]), "+f"(c[2]), "+f"(c[3])
        : "r"(a0), "r"(a1), "r"(a2), "r"(a3), "r"(b0), "r"(b1));
}
__device__ __forceinline__ void ldsm4(uint32_t& r0, uint32_t& r1, uint32_t& r2,
                                      uint32_t& r3, uint32_t addr) {
    asm volatile("ldmatrix.sync.aligned.m8n8.x4.shared.b16 {%0,%1,%2,%3}, [%4];"
                 : "=r"(r0), "=r"(r1), "=r"(r2), "=r"(r3) : "r"(addr));
}
// split fp32 pair -> f16x2 hi, e4m3x2 of value, e4m3x2 of (lo*LSCALE)
__device__ __forceinline__ void splitq(float v0, float v1, uint32_t& hp,
                                       uint32_t& qh, uint32_t& ql) {
    hp = f16pack(v0, v1);
    float2 h = f16dec(hp);
    qh = pk_e4m3(v0, v1);
    ql = pk_e4m3((v0 - h.x) * LSCALE, (v1 - h.y) * LSCALE);
}

// ---------------- Frobenius norm per batch ----------------
__global__ void norm_kernel(const float* __restrict__ x) {
    const int b = blockIdx.x;
    const float4* xb = (const float4*)(x + (size_t)b * MAT);
    float s = 0.f;
    for (int i = threadIdx.x; i < MAT / 4; i += blockDim.x) {
        float4 v = xb[i];
        s += v.x * v.x + v.y * v.y + v.z * v.z + v.w * v.w;
    }
    __shared__ float red[8];
    #pragma unroll
    for (int o = 16; o; o >>= 1) s += __shfl_xor_sync(0xFFFFFFFFu, s, o);
    if ((threadIdx.x & 31) == 0) red[threadIdx.x >> 5] = s;
    __syncthreads();
    if (threadIdx.x < 32) {
        s = (threadIdx.x < (int)(blockDim.x >> 5)) ? red[threadIdx.x] : 0.f;
        #pragma unroll
        for (int o = 16; o; o >>= 1) s += __shfl_xor_sync(0xFFFFFFFFu, s, o);
        if (threadIdx.x == 0) g_norm[b] = sqrtf(s);
    }
}

// ---------------- Y0 = split(x / normA) ----------------
__global__ void init_kernel(const float* __restrict__ x, u16* __restrict__ YH,
                            char* __restrict__ YFh, char* __restrict__ YFl) {
    const int i = blockIdx.x * blockDim.x + threadIdx.x;   // 4 elements
    if (i >= BATCH * MAT / 4) return;
    const int b = i / (MAT / 4);
    const float inv = 1.0f / g_norm[b];
    float4 v = ((const float4*)x)[i];
    uint32_t hp0, qh0, ql0, hp1, qh1, ql1;
    splitq(v.x * inv, v.y * inv, hp0, qh0, ql0);
    splitq(v.z * inv, v.w * inv, hp1, qh1, ql1);
    ((uint2*)YH)[i] = make_uint2(hp0, hp1);
    ((uint32_t*)YFh)[i] = qh0 | (qh1 << 16);
    ((uint32_t*)YFl)[i] = ql0 | (ql1 << 16);
}

// ---------------- Z1 = T0 = split(1.5 I - 0.5 * x / normA), exact from x ----------------
__global__ void zt_kernel(const float* __restrict__ x, u16* __restrict__ ZH,
                          char* __restrict__ ZFh, char* __restrict__ ZFl) {
    const int i = blockIdx.x * blockDim.x + threadIdx.x;   // 4 elements
    if (i >= BATCH * MAT / 4) return;
    const int b = i / (MAT / 4);
    const float inv = -0.5f / g_norm[b];
    float4 v = ((const float4*)x)[i];
    const int e0 = (4 * i) % MAT;
    const int row = e0 / DIM, col = e0 % DIM;
    float v0 = v.x * inv + ((row == col)     ? 1.5f : 0.0f);
    float v1 = v.y * inv + ((row == col + 1) ? 1.5f : 0.0f);
    float v2 = v.z * inv + ((row == col + 2) ? 1.5f : 0.0f);
    float v3 = v.w * inv + ((row == col + 3) ? 1.5f : 0.0f);
    uint32_t hp0, qh0, ql0, hp1, qh1, ql1;
    splitq(v0, v1, hp0, qh0, ql0);
    splitq(v2, v3, hp1, qh1, ql1);
    ((uint2*)ZH)[i] = make_uint2(hp0, hp1);
    ((uint32_t*)ZFh)[i] = qh0 | (qh1 << 16);
    ((uint32_t*)ZFl)[i] = ql0 | (ql1 << 16);
}

// ---------------- out = (H + l/LSCALE) * sqrt(normA) ----------------
__global__ void final_kernel(const u16* __restrict__ YH, const char* __restrict__ YFl,
                             float* __restrict__ out) {
    const int i = blockIdx.x * blockDim.x + threadIdx.x;   // 4 elements
    if (i >= BATCH * MAT / 4) return;
    const int b = i / (MAT / 4);
    const float s = sqrtf(g_norm[b]);
    uint2 hp = ((const uint2*)YH)[i];
    uint32_t ql = ((const uint32_t*)YFl)[i];
    float2 h01 = f16dec(hp.x);
    float2 h23 = f16dec(hp.y);
    float2 l01 = e4m3_dec2(ql & 0xFFFFu);
    float2 l23 = e4m3_dec2(ql >> 16);
    float4 o;
    o.x = (h01.x + l01.x * INVLS) * s;
    o.y = (h01.y + l01.y * INVLS) * s;
    o.z = (h23.x + l23.x * INVLS) * s;
    o.w = (h23.y + l23.y * INVLS) * s;
    ((float4*)out)[i] = o;
}

// ---------------- hybrid fp16-hh + fp8-corrections symmetric batched GEMM ----------------
// C = A@B: hh exact in fp16 m16n8k16 (fp16 products exact in fp32 accum, lo terms
// ~2^-11); corrections Ah*Bl + Al*Bh fused into ONE e4m3 m16n8k32 MMA per 16
// original k (virtual k = [h-half | l-half]; lo pre-scaled xLSCALE, folded back
// via FFMA x(1/LSCALE)). 64 tensor instructions/stage vs 96 pure-16bit.
// Symmetric: B read as B[n][k], tiles ti<=tj only, mirror via smem transpose.
template <int MODE>
__device__ __forceinline__ void gemm_body(
    const u16* __restrict__ AH, const char* __restrict__ AFh, const char* __restrict__ AFl,
    const u16* __restrict__ BH, const char* __restrict__ BFh, const char* __restrict__ BFl,
    u16* __restrict__ CH, char* __restrict__ CFh, char* __restrict__ CFl,
    int ti, int tj, uint32_t* sm)
{
    const int bm = ti * 128;
    const int bn = tj * 128;
    const int tid = threadIdx.x;
    const int wid = tid >> 5;
    const int lane = tid & 31;
    const int gid = lane >> 2;
    const int tig = lane & 3;
    const int wm = wid >> 2;     // 0..1
    const int wn = wid & 3;      // 0..3

    const uint32_t s_base = smem_u32(sm);

    const int f_q = tid & 3;            // chunk id 0..3
    const int f_row0 = tid >> 2;        // 0..63 (+64 for j=1)
    const bool f_h = (f_q < 2);
    const int f_fq = f_q & 1;           // fp8 chunk within plane

    auto fill = [&](int buf, int kc) {
        const uint32_t base = s_base + (uint32_t)buf * (STAGE_U32 * 4);
        const int koff = kc * BK;       // element == byte offset for fp8
        #pragma unroll
        for (int j = 0; j < 2; ++j) {
            const int row = f_row0 + 64 * j;
            const uint32_t rb = base + (uint32_t)row * (GSTR * 4);
            const size_t ar = (size_t)(bm + row) * DIM + koff;
            const size_t br = (size_t)(bn + row) * DIM + koff;
            cp16(rb + O_AH * 4 + f_q * 16, AH + ar + f_q * 8);
            cp16(rb + O_BH * 4 + f_q * 16, BH + br + f_q * 8);
            cp16(rb + (f_h ? O_AFH * 4 : O_AFL * 4) + f_fq * 16,
                 (f_h ? AFh : AFl) + ar + f_fq * 16);
            cp16(rb + (f_h ? O_BFH * 4 : O_BFL * 4) + f_fq * 16,
                 (f_h ? BFh : BFl) + br + f_fq * 16);
        }
        asm volatile("cp.async.commit_group;" ::: "memory");
    };

    float acc[4][4][4];
    #pragma unroll
    for (int mf = 0; mf < 4; ++mf)
        #pragma unroll
        for (int nf = 0; nf < 4; ++nf)
            #pragma unroll
            for (int e = 0; e < 4; ++e) acc[mf][nf][e] = 0.f;

    // fp16 ldmatrix lane offsets (bytes), proven layout:
    const uint32_t aoff = (uint32_t)((((lane & 7) + ((lane >> 3) & 1) * 8) * GSTR
                                      + (lane >> 4) * 4) * 4);
    const uint32_t boff = (uint32_t)((((lane & 7) + (lane >> 4) * 8) * GSTR
                                      + ((lane >> 3) & 1) * 4) * 4);
    // fp8 ldmatrix lane offsets: A -> matrices (h m0-7, h m8-15, l m0-7, l m8-15)
    const uint32_t aqoff = (uint32_t)(((lane & 7) + ((lane >> 3) & 1) * 8) * (GSTR * 4))
                         + (uint32_t)((lane >> 4) ? O_AFL * 4 : O_AFH * 4);
    // fp8 B -> matrices (l nf0, h nf0, l nf1, h nf1): reg pairs come out (l, h)
    const uint32_t bqoff = (uint32_t)(((lane & 7) + ((lane >> 4) & 1) * 8) * (GSTR * 4))
                         + (uint32_t)(((lane >> 3) & 1) ? O_BFH * 4 : O_BFL * 4);

    const uint32_t aRow = (uint32_t)(wm * 64) * (GSTR * 4);
    const uint32_t bRow = (uint32_t)(wn * 32) * (GSTR * 4);

    fill(0, 0);
    fill(1, 1);

    for (int s = 0; s < NSTAGE; ++s) {
        if (s < NSTAGE - 1) asm volatile("cp.async.wait_group 1;" ::: "memory");
        else                asm volatile("cp.async.wait_group 0;" ::: "memory");
        __syncthreads();

        if (s + 2 < NSTAGE) fill((s + 2) % NBUF, s + 2);

        const uint32_t sb = s_base + (uint32_t)(s % NBUF) * (STAGE_U32 * 4);
        const uint32_t bAh = sb + aRow + aoff;            // O_AH = 0
        const uint32_t bBh = sb + O_BH * 4 + bRow + boff;
        const uint32_t bAq = sb + aRow + aqoff;
        const uint32_t bBq = sb + bRow + bqoff;

        #pragma unroll
        for (int g = 0; g < 2; ++g) {
            const uint32_t k16 = g * 32;   // fp16 slab byte offset
            const uint32_t k8 = g * 16;    // fp8 k-group byte offset
            uint32_t Bhf[4][2], Bqf[4][2];
            #pragma unroll
            for (int nfp = 0; nfp < 2; ++nfp) {
                const uint32_t radd = (uint32_t)(nfp * 16) * (GSTR * 4);
                ldsm4(Bhf[2 * nfp][0], Bhf[2 * nfp][1],
                      Bhf[2 * nfp + 1][0], Bhf[2 * nfp + 1][1], bBh + radd + k16);
                ldsm4(Bqf[2 * nfp][0], Bqf[2 * nfp][1],
                      Bqf[2 * nfp + 1][0], Bqf[2 * nfp + 1][1], bBq + radd + k8);
            }
            #pragma unroll
            for (int p = 0; p < 2; ++p) {
                const uint32_t r0add = (uint32_t)(p * 32) * (GSTR * 4);
                const uint32_t r1add = r0add + (uint32_t)16 * (GSTR * 4);
                uint32_t A0[4], A1[4], Q0[4], Q1[4];
                ldsm4(A0[0], A0[1], A0[2], A0[3], bAh + r0add + k16);
                ldsm4(A1[0], A1[1], A1[2], A1[3], bAh + r1add + k16);
                ldsm4(Q0[0], Q0[1], Q0[2], Q0[3], bAq + r0add + k8);
                ldsm4(Q1[0], Q1[1], Q1[2], Q1[3], bAq + r1add + k8);
                const int m0 = 2 * p, m1 = 2 * p + 1;
                float t[4][4];
                #pragma unroll
                for (int nf = 0; nf < 4; ++nf)   // hh m0 (fp16 exact)
                    mma_f16(acc[m0][nf], A0[0], A0[1], A0[2], A0[3],
                            Bhf[nf][0], Bhf[nf][1]);
                #pragma unroll
                for (int nf = 0; nf < 4; ++nf) {
                    t[nf][0] = 0.f; t[nf][1] = 0.f; t[nf][2] = 0.f; t[nf][3] = 0.f;
                }
                #pragma unroll
                for (int nf = 0; nf < 4; ++nf)   // corr m0 (h*l + l*h)
                    mma_e4m3(t[nf], Q0[0], Q0[1], Q0[2], Q0[3],
                             Bqf[nf][0], Bqf[nf][1]);
                #pragma unroll
                for (int nf = 0; nf < 4; ++nf)   // hh m1
                    mma_f16(acc[m1][nf], A1[0], A1[1], A1[2], A1[3],
                            Bhf[nf][0], Bhf[nf][1]);
                #pragma unroll
                for (int nf = 0; nf < 4; ++nf)   // fold m0
                    #pragma unroll
                    for (int e = 0; e < 4; ++e)
                        acc[m0][nf][e] = fmaf(t[nf][e], INVLS, acc[m0][nf][e]);
                #pragma unroll
                for (int nf = 0; nf < 4; ++nf) {
                    t[nf][0] = 0.f; t[nf][1] = 0.f; t[nf][2] = 0.f; t[nf][3] = 0.f;
                }
                #pragma unroll
                for (int nf = 0; nf < 4; ++nf)   // corr m1
                    mma_e4m3(t[nf], Q1[0], Q1[1], Q1[2], Q1[3],
                             Bqf[nf][0], Bqf[nf][1]);
                #pragma unroll
                for (int nf = 0; nf < 4; ++nf)   // fold m1
                    #pragma unroll
                    for (int e = 0; e < 4; ++e)
                        acc[m1][nf][e] = fmaf(t[nf][e], INVLS, acc[m1][nf][e]);
            }
        }
    }

    // ---------------- epilogue ----------------
    const bool mirror = (ti != tj);
    if (mirror) __syncthreads();   // smem reads done; reuse as transpose buffer

    #pragma unroll
    for (int mf = 0; mf < 4; ++mf) {
        #pragma unroll
        for (int nf = 0; nf < 4; ++nf) {
            float* cr = acc[mf][nf];
            const int lr0 = wm * 64 + mf * 16 + gid;
            const int lr1 = lr0 + 8;
            const int lc = wn * 32 + nf * 8 + 2 * tig;
            const int r0 = bm + lr0, r1 = bm + lr1, cb = bn + lc;
            if (MODE == 1) {
                cr[0] = fmaf(cr[0], -0.5f, (cb == r0)     ? 1.5f : 0.0f);
                cr[1] = fmaf(cr[1], -0.5f, (cb + 1 == r0) ? 1.5f : 0.0f);
                cr[2] = fmaf(cr[2], -0.5f, (cb == r1)     ? 1.5f : 0.0f);
                cr[3] = fmaf(cr[3], -0.5f, (cb + 1 == r1) ? 1.5f : 0.0f);
            }
            uint32_t hp0, qh0, ql0, hp1, qh1, ql1;
            splitq(cr[0], cr[1], hp0, qh0, ql0);
            splitq(cr[2], cr[3], hp1, qh1, ql1);
            *(uint32_t*)(CH + (size_t)r0 * DIM + cb) = hp0;
            *(u16*)(CFh + (size_t)r0 * DIM + cb) = (u16)qh0;
            *(u16*)(CFl + (size_t)r0 * DIM + cb) = (u16)ql0;
            *(uint32_t*)(CH + (size_t)r1 * DIM + cb) = hp1;
            *(u16*)(CFh + (size_t)r1 * DIM + cb) = (u16)qh1;
            *(u16*)(CFl + (size_t)r1 * DIM + cb) = (u16)ql1;
            if (mirror) {
                // element record: f16h | fp8h<<16 | fp8l<<24, stored transposed
                sm[(lc)     * TSTR + lr0] = (hp0 & 0xFFFFu) | ((qh0 & 0xFFu) << 16) | ((ql0 & 0xFFu) << 24);
                sm[(lc + 1) * TSTR + lr0] = (hp0 >> 16) | ((qh0 & 0xFF00u) << 8) | ((ql0 & 0xFF00u) << 16);
                sm[(lc)     * TSTR + lr1] = (hp1 & 0xFFFFu) | ((qh1 & 0xFFu) << 16) | ((ql1 & 0xFFu) << 24);
                sm[(lc + 1) * TSTR + lr1] = (hp1 >> 16) | ((qh1 & 0xFF00u) << 8) | ((ql1 & 0xFF00u) << 16);
            }
        }
    }

    if (mirror) {
        __syncthreads();
        const int q = tid & 63;                  // u32-pair index within dest row
        #pragma unroll
        for (int j = 0; j < 32; ++j) {
            const int c = (tid >> 6) + 4 * j;
            uint2 e = *(const uint2*)(sm + c * TSTR + 2 * q);
            const size_t base = (size_t)(bn + c) * DIM + bm + 2 * q;
            *(uint32_t*)(CH + base) = (e.x & 0xFFFFu) | ((e.y & 0xFFFFu) << 16);
            *(u16*)(CFh + base) = (u16)(((e.x >> 16) & 0xFFu) | (((e.y >> 16) & 0xFFu) << 8));
            *(u16*)(CFl + base) = (u16)((e.x >> 24) | ((e.y >> 24) << 8));
        }
    }
}

template <int MODE>
__global__ void __launch_bounds__(256, 2) gemm_tc(
    const u16* __restrict__ AH, const char* __restrict__ AFh, const char* __restrict__ AFl,
    const u16* __restrict__ BH, const char* __restrict__ BFh, const char* __restrict__ BFl,
    u16* __restrict__ CH, char* __restrict__ CFh, char* __restrict__ CFl) {
    extern __shared__ uint32_t smu[];
    const size_t off = (size_t)blockIdx.z * MAT;
    gemm_body<MODE>(AH + off, AFh + off, AFl + off, BH + off, BFh + off, BFl + off,
                    CH + off, CFh + off, CFl + off,
                    c_ti[blockIdx.x], c_tj[blockIdx.x], smu);
}

// merged launch: y==0 -> C0 = A0@B0 ; y==1 -> C1 = A1@B1 (both MODE 0)
__global__ void __launch_bounds__(256, 2) gemm_dual(
    const u16* __restrict__ A0H, const char* __restrict__ A0Fh, const char* __restrict__ A0Fl,
    const u16* __restrict__ B0H, const char* __restrict__ B0Fh, const char* __restrict__ B0Fl,
    u16* __restrict__ C0H, char* __restrict__ C0Fh, char* __restrict__ C0Fl,
    const u16* __restrict__ A1H, const char* __restrict__ A1Fh, const char* __restrict__ A1Fl,
    const u16* __restrict__ B1H, const char* __restrict__ B1Fh, const char* __restrict__ B1Fl,
    u16* __restrict__ C1H, char* __restrict__ C1Fh, char* __restrict__ C1Fl) {
    extern __shared__ uint32_t smu[];
    const size_t off = (size_t)blockIdx.z * MAT;
    if (blockIdx.y == 0)
        gemm_body<0>(A0H + off, A0Fh + off, A0Fl + off, B0H + off, B0Fh + off, B0Fl + off,
                     C0H + off, C0Fh + off, C0Fl + off,
                     c_ti[blockIdx.x], c_tj[blockIdx.x], smu);
    else
        gemm_body<0>(A1H + off, A1Fh + off, A1Fl + off, B1H + off, B1Fh + off, B1Fl + off,
                     C1H + off, C1Fh + off, C1Fl + off,
                     c_ti[blockIdx.x], c_tj[blockIdx.x], smu);
}

// ---------------- host launcher ----------------
extern "C" void kernel_launch(void* const* d_in, const int* in_sizes, int n_in,
                              void* d_out, int out_size) {
    const float* x = (const float*)d_in[0];
    float* out = (float*)d_out;

    u16 *YHb, *ZHb, *THb;
    char *YFhb, *YFlb, *ZFhb, *ZFlb, *TFhb, *TFlb;
    cudaGetSymbolAddress((void**)&YHb, g_YH);
    cudaGetSymbolAddress((void**)&YFhb, g_YFh);
    cudaGetSymbolAddress((void**)&YFlb, g_YFl);
    cudaGetSymbolAddress((void**)&ZHb, g_ZH);
    cudaGetSymbolAddress((void**)&ZFhb, g_ZFh);
    cudaGetSymbolAddress((void**)&ZFlb, g_ZFl);
    cudaGetSymbolAddress((void**)&THb, g_TH);
    cudaGetSymbolAddress((void**)&TFhb, g_TFh);
    cudaGetSymbolAddress((void**)&TFlb, g_TFl);
    const size_t half = (size_t)BATCH * MAT;
    u16*  YH[2] = {YHb, YHb + half};
    char* YFh[2] = {YFhb, YFhb + half};
    char* YFl[2] = {YFlb, YFlb + half};
    u16*  ZH[2] = {ZHb, ZHb + half};
    char* ZFh[2] = {ZFhb, ZFhb + half};
    char* ZFl[2] = {ZFlb, ZFlb + half};

    cudaFuncSetAttribute(gemm_tc<0>, cudaFuncAttributeMaxDynamicSharedMemorySize, SMEM_BYTES);
    cudaFuncSetAttribute(gemm_tc<1>, cudaFuncAttributeMaxDynamicSharedMemorySize, SMEM_BYTES);
    cudaFuncSetAttribute(gemm_dual, cudaFuncAttributeMaxDynamicSharedMemorySize, SMEM_BYTES);

    norm_kernel<<<BATCH, 256>>>(x);
    const int total4 = BATCH * MAT / 4;
    init_kernel<<<(total4 + 255) / 256, 256>>>(x, YH[0], YFh[0], YFl[0]);

    // iter 0 (Z0 = I): T0 = 1.5I - 0.5*Y0 (exact from x) stored as Z[0]; Y1 = Y0 @ T0
    zt_kernel<<<(total4 + 255) / 256, 256>>>(x, ZH[0], ZFh[0], ZFl[0]);

    dim3 ggrid(10, 1, BATCH);
    dim3 dgrid(10, 2, BATCH);
    gemm_tc<0><<<ggrid, 256, SMEM_BYTES>>>(YH[0], YFh[0], YFl[0],
                                           ZH[0], ZFh[0], ZFl[0],
                                           YH[1], YFh[1], YFl[1]);
    int ycur = 1, zcur = 0;

    for (int it = 1; it < NUM_ITER; ++it) {
        // T = 1.5 I - 0.5 * Z @ Y
        gemm_tc<1><<<ggrid, 256, SMEM_BYTES>>>(ZH[zcur], ZFh[zcur], ZFl[zcur],
                                               YH[ycur], YFh[ycur], YFl[ycur],
                                               THb, TFhb, TFlb);
        if (it < NUM_ITER - 1) {
            // merged: Y' = Y @ T and Z' = T @ Z
            gemm_dual<<<dgrid, 256, SMEM_BYTES>>>(
                YH[ycur], YFh[ycur], YFl[ycur], THb, TFhb, TFlb,
                YH[1 - ycur], YFh[1 - ycur], YFl[1 - ycur],
                THb, TFhb, TFlb, ZH[zcur], ZFh[zcur], ZFl[zcur],
                ZH[1 - zcur], ZFh[1 - zcur], ZFl[1 - zcur]);
            ycur ^= 1; zcur ^= 1;
        } else {
            gemm_tc<0><<<ggrid, 256, SMEM_BYTES>>>(YH[ycur], YFh[ycur], YFl[ycur],
                                                   THb, TFhb, TFlb,
                                                   YH[1 - ycur], YFh[1 - ycur], YFl[1 - ycur]);
            ycur ^= 1;
        }
    }

    final_kernel<<<(total4 + 255) / 256, 256>>>(YH[ycur], YFl[ycur], out);
}